// round 7
// baseline (speedup 1.0000x reference)
#include <cuda_runtime.h>
#include <cuda_bf16.h>
#include <cstdint>

__host__ __device__ constexpr int PC4(int x) {
    return ((x >> 0) & 1) + ((x >> 1) & 1) + ((x >> 2) & 1) + ((x >> 3) & 1);
}
__host__ __device__ constexpr float SGN(int a, int b) {
    int s = 0; int aa = a >> 1;
    while (aa) { s += PC4(aa & b); aa >>= 1; }
    return (s & 1) ? -1.0f : 1.0f;
}
struct GPTab { int a[192]; int b[192]; int k[192]; float s[192]; };
__host__ __device__ constexpr GPTab make_gp() {
    GPTab t{}; int n = 0;
    for (int a = 0; a < 16; a++)
        for (int b = 0; b < 16; b++)
            if (!(a & b & 1)) { t.a[n]=a; t.b[n]=b; t.k[n]=a^b; t.s[n]=SGN(a,b); n++; }
    return t;
}
struct JTab { int a[81]; int b[81]; int k[81]; float s[81]; };
__host__ __device__ constexpr JTab make_j() {
    JTab t{}; int n = 0;
    for (int i = 0; i < 16; i++)
        for (int j = 0; j < 16; j++)
            if ((i | j) == 15) {
                int p = i^15, q = j^15, k = i&j, r = k^15;
                t.a[n]=i; t.b[n]=j; t.k[n]=k;
                t.s[n]=SGN(i,p)*SGN(j,q)*SGN(p,q)*SGN(k,r); n++;
            }
    return t;
}
__device__ constexpr GPTab GPT = make_gp();
__device__ constexpr JTab  JT  = make_j();
__device__ constexpr int PCY[16] = {0,1,1,2,1,2,2,3,1,2,2,3,2,3,3,4};

// D[16p x 8j] += A[16p x 16i](row) * B[16i x 8j](col)
#define MMA(d, a, b) \
    asm("mma.sync.aligned.m16n8k16.row.col.f32.bf16.bf16.f32 " \
        "{%0,%1,%2,%3}, {%4,%5,%6,%7}, {%8,%9}, {%0,%1,%2,%3};" \
        : "+f"(d[0]), "+f"(d[1]), "+f"(d[2]), "+f"(d[3]) \
        : "r"(a[0]), "r"(a[1]), "r"(a[2]), "r"(a[3]), "r"(b[0]), "r"(b[1]))

#define THREADS 512
#define JSTR 136                    // w row: 64 i * 2B + 8B pad
#define WPL  (32 * JSTR)            // 4352 per (ws,b,hl) plane
#define WSM_BYTES (36 * WPL)        // 156672
#define PSTR 48                     // x row: 16 i * 2B + 16B pad
#define YPL  (32 * PSTR + 8)        // 1544
#define XHL  (16 * YPL)             // 24704
#define XSM_BYTES (2 * XHL)         // 49408
#define EX_PSTR 549                 // floats; banks 5r+2q all-distinct
#define EX_JSTR 17
#define UNION_BYTES 70656           // >= max(XSM_BYTES, exch 70248)
#define SMEM_BYTES (WSM_BYTES + UNION_BYTES)   // 227328

__device__ __forceinline__ uint32_t lds32(const char* p) { return *(const uint32_t*)p; }

__global__ __launch_bounds__(THREADS, 1)
void gbl_kernel(const float* __restrict__ x, const float* __restrict__ ref,
                const float* __restrict__ wg1, const float* __restrict__ wg2,
                const float* __restrict__ wj1, const float* __restrict__ wj2,
                float* __restrict__ out, int nPos)
{
    extern __shared__ char sm[];
    char*  wsm  = sm;                          // [(ws*9+b)*2+hl][j 32][i 64] bf16
    char*  xsm  = sm + WSM_BYTES;              // [hl][y 16][p 32][i 16] bf16
    float* exch = (float*)(sm + WSM_BYTES);    // overlaid: [p*549 + j*17 + y]

    const int tid  = threadIdx.x;
    const int wid  = tid >> 5;
    const int lane = tid & 31;
    const int ws = wid >> 3;       // weight set handled by this warp
    const int pt = (wid >> 2) & 1; // position tile (16)
    const int jt = wid & 3;        // channel tile (8)
    const int r  = lane >> 2;
    const int q  = lane & 3;

    const int group  = blockIdx.y;
    const int branch = group >> 1;
    const int chalf  = group & 1;
    const float* wA = branch ? wj1 : wg1;
    const float* wB = branch ? wj2 : wg2;

    // ---- stage weights (fp32 -> bf16 hi/lo) ----
    for (int e = tid; e < 36864; e += THREADS) {
        int wss = e / 18432;
        int rem = e - wss * 18432;
        int j = rem / 576;
        int rem2 = rem - j * 576;
        int i = rem2 / 9;
        int b = rem2 - i * 9;
        const float* src = wss ? wB : wA;
        float v = src[(chalf * 32 + j) * 576 + i * 9 + b];
        __nv_bfloat16 h = __float2bfloat16(v);
        __nv_bfloat16 l = __float2bfloat16(v - __bfloat162float(h));
        char* rp = wsm + ((wss * 9 + b) * 2) * WPL + j * JSTR + i * 2;
        *(__nv_bfloat16*)rp = h;
        *(__nv_bfloat16*)(rp + WPL) = l;
    }

    const int nChunk = nPos >> 5;
    const float4* xg4 = (const float4*)x;

    const char* wbase = wsm + (jt * 8 + r) * JSTR + q * 4;
    const char* xbase = xsm + (pt * 16 + r) * PSTR + q * 4;

    for (int chunk = blockIdx.x; chunk < nChunk; chunk += gridDim.x) {
        const int p0 = chunk << 5;

        float D[16][4];
        #pragma unroll
        for (int y = 0; y < 16; y++)
            #pragma unroll
            for (int k = 0; k < 4; k++) D[y][k] = 0.0f;

        for (int ib = 0; ib < 4; ib++) {
            __syncthreads();
            // ---- stage x k-block: fp32 -> [hl][y][p][i] bf16 ----
            #pragma unroll
            for (int k = 0; k < 2; k++) {
                int f = tid + k * THREADS;
                int q4 = f & 3, ip = (f >> 2) & 7, p = f >> 5;
                const float4* g = xg4 + ((size_t)(p0 + p) * 64 + ib * 16 + 2 * ip) * 4 + q4;
                float4 v0 = g[0];
                float4 v1 = g[4];
                float e0[4] = {v0.x, v0.y, v0.z, v0.w};
                float e1[4] = {v1.x, v1.y, v1.z, v1.w};
                #pragma unroll
                for (int c = 0; c < 4; c++) {
                    int y = q4 * 4 + c;
                    __nv_bfloat16 h0 = __float2bfloat16(e0[c]);
                    __nv_bfloat16 h1 = __float2bfloat16(e1[c]);
                    __nv_bfloat16 l0 = __float2bfloat16(e0[c] - __bfloat162float(h0));
                    __nv_bfloat16 l1 = __float2bfloat16(e1[c] - __bfloat162float(h1));
                    uint32_t hw = (uint32_t)__bfloat16_as_ushort(h0) |
                                  ((uint32_t)__bfloat16_as_ushort(h1) << 16);
                    uint32_t lw = (uint32_t)__bfloat16_as_ushort(l0) |
                                  ((uint32_t)__bfloat16_as_ushort(l1) << 16);
                    char* d0 = xsm + y * YPL + p * PSTR + ip * 4;
                    *(uint32_t*)d0 = hw;
                    *(uint32_t*)(d0 + XHL) = lw;
                }
            }
            __syncthreads();

            // ---- resident hi w fragments for this k-block (own ws) ----
            uint32_t Bh[9][2];
            #pragma unroll
            for (int b = 0; b < 9; b++) {
                const char* bp = wbase + ((ws * 9 + b) * 2) * WPL + ib * 32;
                Bh[b][0] = lds32(bp);
                Bh[b][1] = lds32(bp + 16);
            }

            #pragma unroll
            for (int t = 0; t < 8; t++) {
                const int ye = 2 * t, yo = 2 * t + 1;
                const int pe = PCY[ye], po = PCY[yo], bs = 4 + po;
                uint32_t Ax[2][2][4];   // [even/odd y][hi/lo]
                #pragma unroll
                for (int yy = 0; yy < 2; yy++)
                    #pragma unroll
                    for (int hl = 0; hl < 2; hl++) {
                        const char* ap = xbase + hl * XHL + (ye + yy) * YPL;
                        Ax[yy][hl][0] = lds32(ap);
                        Ax[yy][hl][1] = lds32(ap + 8 * PSTR);
                        Ax[yy][hl][2] = lds32(ap + 16);
                        Ax[yy][hl][3] = lds32(ap + 8 * PSTR + 16);
                    }
                // transient lo w fragments (3 maps)
                uint32_t Bl_pe[2], Bl_po[2], Bl_bs[2];
                {
                    const char* lp;
                    lp = wbase + ((ws * 9 + pe) * 2 + 1) * WPL + ib * 32;
                    Bl_pe[0] = lds32(lp); Bl_pe[1] = lds32(lp + 16);
                    lp = wbase + ((ws * 9 + po) * 2 + 1) * WPL + ib * 32;
                    Bl_po[0] = lds32(lp); Bl_po[1] = lds32(lp + 16);
                    lp = wbase + ((ws * 9 + bs) * 2 + 1) * WPL + ib * 32;
                    Bl_bs[0] = lds32(lp); Bl_bs[1] = lds32(lp + 16);
                }
                float* De = D[ye];
                float* Do = D[yo];
                MMA(De, Ax[0][0], Bh[pe]);   // wh*xh
                MMA(De, Ax[0][1], Bh[pe]);   // wh*xl
                MMA(De, Ax[0][0], Bl_pe);    // wl*xh
                MMA(Do, Ax[1][0], Bh[po]);
                MMA(Do, Ax[1][1], Bh[po]);
                MMA(Do, Ax[1][0], Bl_po);
                MMA(Do, Ax[0][0], Bh[bs]);   // e0-shift: x[ye] -> E[yo]
                MMA(Do, Ax[0][1], Bh[bs]);
                MMA(Do, Ax[0][0], Bl_bs);
            }
        }

        // ---- exchange: ws=1 exports E1, ws=0 runs bilinear + store ----
        __syncthreads();
        if (ws == 1) {
            #pragma unroll
            for (int e = 0; e < 4; e++) {
                const int pl = pt * 16 + r + ((e >> 1) << 3);
                const int jl = jt * 8 + 2 * q + (e & 1);
                float* ex = exch + pl * EX_PSTR + jl * EX_JSTR;
                #pragma unroll
                for (int y = 0; y < 16; y++) ex[y] = D[y][e];
            }
        }
        __syncthreads();
        if (ws == 0) {
            #pragma unroll
            for (int e = 0; e < 4; e++) {
                const int pl = pt * 16 + r + ((e >> 1) << 3);
                const int jl = jt * 8 + 2 * q + (e & 1);
                const float* ex = exch + pl * EX_PSTR + jl * EX_JSTR;
                float E1[16];
                #pragma unroll
                for (int y = 0; y < 16; y++) E1[y] = ex[y];

                const int p = p0 + pl;
                float o[16];
                #pragma unroll
                for (int y = 0; y < 16; y++) o[y] = 0.0f;

                if (branch == 0) {
                    #pragma unroll
                    for (int n = 0; n < 192; n++)
                        o[GPT.k[n]] += GPT.s[n] * D[GPT.a[n]][e] * E1[GPT.b[n]];
                    #pragma unroll
                    for (int y = 0; y < 16; y++) o[y] *= 1e-5f;
                } else {
                    #pragma unroll
                    for (int n = 0; n < 81; n++)
                        o[JT.k[n]] += JT.s[n] * D[JT.a[n]][e] * E1[JT.b[n]];
                    const float rr = __ldg(ref + (size_t)p * 16 + 15);
                    #pragma unroll
                    for (int y = 0; y < 16; y++) o[y] *= rr;
                }

                const int co = branch * 64 + chalf * 32 + jl;
                float4* op = (float4*)(out + ((size_t)p * 128 + co) * 16);
                op[0] = make_float4(o[0],  o[1],  o[2],  o[3]);
                op[1] = make_float4(o[4],  o[5],  o[6],  o[7]);
                op[2] = make_float4(o[8],  o[9],  o[10], o[11]);
                op[3] = make_float4(o[12], o[13], o[14], o[15]);
            }
        }
    }
}

extern "C" void kernel_launch(void* const* d_in, const int* in_sizes, int n_in,
                              void* d_out, int out_size) {
    const float* x   = (const float*)d_in[0];
    const float* ref = (const float*)d_in[1];
    const float* wg1 = (const float*)d_in[2];
    const float* wg2 = (const float*)d_in[3];
    const float* wj1 = (const float*)d_in[4];
    const float* wj2 = (const float*)d_in[5];
    float* out = (float*)d_out;

    const int nPos = in_sizes[0] / (64 * 16);   // 16384

    cudaFuncSetAttribute(gbl_kernel, cudaFuncAttributeMaxDynamicSharedMemorySize, SMEM_BYTES);
    dim3 grid(37, 4);
    gbl_kernel<<<grid, THREADS, SMEM_BYTES>>>(x, ref, wg1, wg2, wj1, wj2, out, nPos);
}

// round 8
// speedup vs baseline: 1.0003x; 1.0003x over previous
#include <cuda_runtime.h>
#include <cuda_bf16.h>
#include <cstdint>

__host__ __device__ constexpr int PC4(int x) {
    return ((x >> 0) & 1) + ((x >> 1) & 1) + ((x >> 2) & 1) + ((x >> 3) & 1);
}
__host__ __device__ constexpr float SGN(int a, int b) {
    int s = 0; int aa = a >> 1;
    while (aa) { s += PC4(aa & b); aa >>= 1; }
    return (s & 1) ? -1.0f : 1.0f;
}
struct GPTab { int a[192]; int b[192]; int k[192]; float s[192]; };
__host__ __device__ constexpr GPTab make_gp() {
    GPTab t{}; int n = 0;
    for (int a = 0; a < 16; a++)
        for (int b = 0; b < 16; b++)
            if (!(a & b & 1)) { t.a[n]=a; t.b[n]=b; t.k[n]=a^b; t.s[n]=SGN(a,b); n++; }
    return t;
}
struct JTab { int a[81]; int b[81]; int k[81]; float s[81]; };
__host__ __device__ constexpr JTab make_j() {
    JTab t{}; int n = 0;
    for (int i = 0; i < 16; i++)
        for (int j = 0; j < 16; j++)
            if ((i | j) == 15) {
                int p = i^15, q = j^15, k = i&j, r = k^15;
                t.a[n]=i; t.b[n]=j; t.k[n]=k;
                t.s[n]=SGN(i,p)*SGN(j,q)*SGN(p,q)*SGN(k,r); n++;
            }
    return t;
}
__device__ constexpr GPTab GPT = make_gp();
__device__ constexpr JTab  JT  = make_j();
__device__ constexpr int PCY[16] = {0,1,1,2,1,2,2,3,1,2,2,3,2,3,3,4};

// D[16p x 8j] += A[16p x 16i](row) * B[16i x 8j](col)
#define MMA(d, a, b) \
    asm("mma.sync.aligned.m16n8k16.row.col.f32.bf16.bf16.f32 " \
        "{%0,%1,%2,%3}, {%4,%5,%6,%7}, {%8,%9}, {%0,%1,%2,%3};" \
        : "+f"(d[0]), "+f"(d[1]), "+f"(d[2]), "+f"(d[3]) \
        : "r"(a[0]), "r"(a[1]), "r"(a[2]), "r"(a[3]), "r"(b[0]), "r"(b[1]))

#define THREADS 512
#define JSTR 136                    // w row: 64 i * 2B + 8B pad
#define WPL  (32 * JSTR)            // 4352 per (ws,b,hl) plane
#define WSM_BYTES (36 * WPL)        // 156672
#define PSTR 48                     // x row: 16 i * 2B + 16B pad
#define YPL  (32 * PSTR + 8)        // 1544
#define XHL  (16 * YPL)             // 24704
#define XSM_BYTES (2 * XHL)         // 49408
#define EX_PSTR 549                 // floats; banks 5r+2q all-distinct
#define EX_JSTR 17
#define UNION_BYTES 70656           // >= max(XSM_BYTES, exch 70248)
#define SMEM_BYTES (WSM_BYTES + UNION_BYTES)   // 227328

__device__ __forceinline__ uint32_t lds32(const char* p) { return *(const uint32_t*)p; }

__global__ __launch_bounds__(THREADS, 1)
void gbl_kernel(const float* __restrict__ x, const float* __restrict__ ref,
                const float* __restrict__ wg1, const float* __restrict__ wg2,
                const float* __restrict__ wj1, const float* __restrict__ wj2,
                float* __restrict__ out, int nPos)
{
    extern __shared__ char sm[];
    char*  wsm  = sm;                          // [(ws*9+b)*2+hl][j 32][i 64] bf16
    char*  xsm  = sm + WSM_BYTES;              // [hl][y 16][p 32][i 16] bf16
    float* exch = (float*)(sm + WSM_BYTES);    // overlaid: [p*549 + j*17 + y]

    const int tid  = threadIdx.x;
    const int wid  = tid >> 5;
    const int lane = tid & 31;
    const int ws = wid >> 3;       // weight set handled by this warp
    const int pt = (wid >> 2) & 1; // position tile (16)
    const int jt = wid & 3;        // channel tile (8)
    const int r  = lane >> 2;
    const int q  = lane & 3;

    const int group  = blockIdx.y;
    const int branch = group >> 1;
    const int chalf  = group & 1;
    const float* wA = branch ? wj1 : wg1;
    const float* wB = branch ? wj2 : wg2;

    // ---- stage weights (fp32 -> bf16 hi/lo) ----
    for (int e = tid; e < 36864; e += THREADS) {
        int wss = e / 18432;
        int rem = e - wss * 18432;
        int j = rem / 576;
        int rem2 = rem - j * 576;
        int i = rem2 / 9;
        int b = rem2 - i * 9;
        const float* src = wss ? wB : wA;
        float v = src[(chalf * 32 + j) * 576 + i * 9 + b];
        __nv_bfloat16 h = __float2bfloat16(v);
        __nv_bfloat16 l = __float2bfloat16(v - __bfloat162float(h));
        char* rp = wsm + ((wss * 9 + b) * 2) * WPL + j * JSTR + i * 2;
        *(__nv_bfloat16*)rp = h;
        *(__nv_bfloat16*)(rp + WPL) = l;
    }

    const int nChunk = nPos >> 5;
    const float4* xg4 = (const float4*)x;

    const char* wbase = wsm + (jt * 8 + r) * JSTR + q * 4;
    const char* xbase = xsm + (pt * 16 + r) * PSTR + q * 4;

    for (int chunk = blockIdx.x; chunk < nChunk; chunk += gridDim.x) {
        const int p0 = chunk << 5;

        float D[16][4];
        #pragma unroll
        for (int y = 0; y < 16; y++)
            #pragma unroll
            for (int k = 0; k < 4; k++) D[y][k] = 0.0f;

        for (int ib = 0; ib < 4; ib++) {
            __syncthreads();
            // ---- stage x k-block: fp32 -> [hl][y][p][i] bf16 ----
            #pragma unroll
            for (int k = 0; k < 2; k++) {
                int f = tid + k * THREADS;
                int q4 = f & 3, ip = (f >> 2) & 7, p = f >> 5;
                const float4* g = xg4 + ((size_t)(p0 + p) * 64 + ib * 16 + 2 * ip) * 4 + q4;
                float4 v0 = g[0];
                float4 v1 = g[4];
                float e0[4] = {v0.x, v0.y, v0.z, v0.w};
                float e1[4] = {v1.x, v1.y, v1.z, v1.w};
                #pragma unroll
                for (int c = 0; c < 4; c++) {
                    int y = q4 * 4 + c;
                    __nv_bfloat16 h0 = __float2bfloat16(e0[c]);
                    __nv_bfloat16 h1 = __float2bfloat16(e1[c]);
                    __nv_bfloat16 l0 = __float2bfloat16(e0[c] - __bfloat162float(h0));
                    __nv_bfloat16 l1 = __float2bfloat16(e1[c] - __bfloat162float(h1));
                    uint32_t hw = (uint32_t)__bfloat16_as_ushort(h0) |
                                  ((uint32_t)__bfloat16_as_ushort(h1) << 16);
                    uint32_t lw = (uint32_t)__bfloat16_as_ushort(l0) |
                                  ((uint32_t)__bfloat16_as_ushort(l1) << 16);
                    char* d0 = xsm + y * YPL + p * PSTR + ip * 4;
                    *(uint32_t*)d0 = hw;
                    *(uint32_t*)(d0 + XHL) = lw;
                }
            }
            __syncthreads();

            // ---- resident hi w fragments for this k-block (own ws) ----
            uint32_t Bh[9][2];
            #pragma unroll
            for (int b = 0; b < 9; b++) {
                const char* bp = wbase + ((ws * 9 + b) * 2) * WPL + ib * 32;
                Bh[b][0] = lds32(bp);
                Bh[b][1] = lds32(bp + 16);
            }

            #pragma unroll
            for (int t = 0; t < 8; t++) {
                const int ye = 2 * t, yo = 2 * t + 1;
                const int pe = PCY[ye], po = PCY[yo], bs = 4 + po;
                uint32_t Ax[2][2][4];   // [even/odd y][hi/lo]
                #pragma unroll
                for (int yy = 0; yy < 2; yy++)
                    #pragma unroll
                    for (int hl = 0; hl < 2; hl++) {
                        const char* ap = xbase + hl * XHL + (ye + yy) * YPL;
                        Ax[yy][hl][0] = lds32(ap);
                        Ax[yy][hl][1] = lds32(ap + 8 * PSTR);
                        Ax[yy][hl][2] = lds32(ap + 16);
                        Ax[yy][hl][3] = lds32(ap + 8 * PSTR + 16);
                    }
                // transient lo w fragments (3 maps)
                uint32_t Bl_pe[2], Bl_po[2], Bl_bs[2];
                {
                    const char* lp;
                    lp = wbase + ((ws * 9 + pe) * 2 + 1) * WPL + ib * 32;
                    Bl_pe[0] = lds32(lp); Bl_pe[1] = lds32(lp + 16);
                    lp = wbase + ((ws * 9 + po) * 2 + 1) * WPL + ib * 32;
                    Bl_po[0] = lds32(lp); Bl_po[1] = lds32(lp + 16);
                    lp = wbase + ((ws * 9 + bs) * 2 + 1) * WPL + ib * 32;
                    Bl_bs[0] = lds32(lp); Bl_bs[1] = lds32(lp + 16);
                }
                float* De = D[ye];
                float* Do = D[yo];
                MMA(De, Ax[0][0], Bh[pe]);   // wh*xh
                MMA(De, Ax[0][1], Bh[pe]);   // wh*xl
                MMA(De, Ax[0][0], Bl_pe);    // wl*xh
                MMA(Do, Ax[1][0], Bh[po]);
                MMA(Do, Ax[1][1], Bh[po]);
                MMA(Do, Ax[1][0], Bl_po);
                MMA(Do, Ax[0][0], Bh[bs]);   // e0-shift: x[ye] -> E[yo]
                MMA(Do, Ax[0][1], Bh[bs]);
                MMA(Do, Ax[0][0], Bl_bs);
            }
        }

        // ---- exchange: ws=1 exports E1, ws=0 runs bilinear + store ----
        __syncthreads();
        if (ws == 1) {
            #pragma unroll
            for (int e = 0; e < 4; e++) {
                const int pl = pt * 16 + r + ((e >> 1) << 3);
                const int jl = jt * 8 + 2 * q + (e & 1);
                float* ex = exch + pl * EX_PSTR + jl * EX_JSTR;
                #pragma unroll
                for (int y = 0; y < 16; y++) ex[y] = D[y][e];
            }
        }
        __syncthreads();
        if (ws == 0) {
            #pragma unroll
            for (int e = 0; e < 4; e++) {
                const int pl = pt * 16 + r + ((e >> 1) << 3);
                const int jl = jt * 8 + 2 * q + (e & 1);
                const float* ex = exch + pl * EX_PSTR + jl * EX_JSTR;
                float E1[16];
                #pragma unroll
                for (int y = 0; y < 16; y++) E1[y] = ex[y];

                const int p = p0 + pl;
                float o[16];
                #pragma unroll
                for (int y = 0; y < 16; y++) o[y] = 0.0f;

                if (branch == 0) {
                    #pragma unroll
                    for (int n = 0; n < 192; n++)
                        o[GPT.k[n]] += GPT.s[n] * D[GPT.a[n]][e] * E1[GPT.b[n]];
                    #pragma unroll
                    for (int y = 0; y < 16; y++) o[y] *= 1e-5f;
                } else {
                    #pragma unroll
                    for (int n = 0; n < 81; n++)
                        o[JT.k[n]] += JT.s[n] * D[JT.a[n]][e] * E1[JT.b[n]];
                    const float rr = __ldg(ref + (size_t)p * 16 + 15);
                    #pragma unroll
                    for (int y = 0; y < 16; y++) o[y] *= rr;
                }

                const int co = branch * 64 + chalf * 32 + jl;
                float4* op = (float4*)(out + ((size_t)p * 128 + co) * 16);
                op[0] = make_float4(o[0],  o[1],  o[2],  o[3]);
                op[1] = make_float4(o[4],  o[5],  o[6],  o[7]);
                op[2] = make_float4(o[8],  o[9],  o[10], o[11]);
                op[3] = make_float4(o[12], o[13], o[14], o[15]);
            }
        }
    }
}

extern "C" void kernel_launch(void* const* d_in, const int* in_sizes, int n_in,
                              void* d_out, int out_size) {
    const float* x   = (const float*)d_in[0];
    const float* ref = (const float*)d_in[1];
    const float* wg1 = (const float*)d_in[2];
    const float* wg2 = (const float*)d_in[3];
    const float* wj1 = (const float*)d_in[4];
    const float* wj2 = (const float*)d_in[5];
    float* out = (float*)d_out;

    const int nPos = in_sizes[0] / (64 * 16);   // 16384

    cudaFuncSetAttribute(gbl_kernel, cudaFuncAttributeMaxDynamicSharedMemorySize, SMEM_BYTES);
    dim3 grid(37, 4);
    gbl_kernel<<<grid, THREADS, SMEM_BYTES>>>(x, ref, wg1, wg2, wj1, wj2, out, nPos);
}

// round 10
// speedup vs baseline: 1.0597x; 1.0594x over previous
#include <cuda_runtime.h>
#include <cuda_bf16.h>
#include <cstdint>

__host__ __device__ constexpr int PC4(int x) {
    return ((x >> 0) & 1) + ((x >> 1) & 1) + ((x >> 2) & 1) + ((x >> 3) & 1);
}
__host__ __device__ constexpr float SGN(int a, int b) {
    int s = 0; int aa = a >> 1;
    while (aa) { s += PC4(aa & b); aa >>= 1; }
    return (s & 1) ? -1.0f : 1.0f;
}
struct GPTab { int a[192]; int b[192]; int k[192]; float s[192]; };
__host__ __device__ constexpr GPTab make_gp() {
    GPTab t{}; int n = 0;
    for (int a = 0; a < 16; a++)
        for (int b = 0; b < 16; b++)
            if (!(a & b & 1)) { t.a[n]=a; t.b[n]=b; t.k[n]=a^b; t.s[n]=SGN(a,b); n++; }
    return t;
}
struct JTab { int a[81]; int b[81]; int k[81]; float s[81]; };
__host__ __device__ constexpr JTab make_j() {
    JTab t{}; int n = 0;
    for (int i = 0; i < 16; i++)
        for (int j = 0; j < 16; j++)
            if ((i | j) == 15) {
                int p = i^15, q = j^15, k = i&j, r = k^15;
                t.a[n]=i; t.b[n]=j; t.k[n]=k;
                t.s[n]=SGN(i,p)*SGN(j,q)*SGN(p,q)*SGN(k,r); n++;
            }
    return t;
}
__device__ constexpr GPTab GPT = make_gp();
__device__ constexpr JTab  JT  = make_j();
__device__ constexpr int PCY[16] = {0,1,1,2,1,2,2,3,1,2,2,3,2,3,3,4};

#define MMA(d, a, b) \
    asm("mma.sync.aligned.m16n8k16.row.col.f32.bf16.bf16.f32 " \
        "{%0,%1,%2,%3}, {%4,%5,%6,%7}, {%8,%9}, {%0,%1,%2,%3};" \
        : "+f"(d[0]), "+f"(d[1]), "+f"(d[2]), "+f"(d[3]) \
        : "r"(a[0]), "r"(a[1]), "r"(a[2]), "r"(a[3]), "r"(b[0]), "r"(b[1]))

__device__ __forceinline__ void ldmx4(uint32_t* r, uint32_t a) {
    asm volatile("ldmatrix.sync.aligned.m8n8.x4.shared.b16 {%0,%1,%2,%3}, [%4];"
        : "=r"(r[0]), "=r"(r[1]), "=r"(r[2]), "=r"(r[3]) : "r"(a));
}
__device__ __forceinline__ void ldmx2(uint32_t* r, uint32_t a) {
    asm volatile("ldmatrix.sync.aligned.m8n8.x2.shared.b16 {%0,%1}, [%2];"
        : "=r"(r[0]), "=r"(r[1]) : "r"(a));
}
__device__ __forceinline__ uint32_t smem_u32(const void* p) {
    uint32_t a;
    asm("{ .reg .u64 t; cvta.to.shared.u64 t, %1; cvt.u32.u64 %0, t; }" : "=r"(a) : "l"(p));
    return a;
}

#define THREADS 256
#define JSTR 144
#define WPL  (32 * JSTR)            // 4608 per (ws,b,hl) plane
#define WSM_BYTES (36 * WPL)        // 165888
#define PSTR 48
#define YPL  (32 * PSTR + 16)       // 1552 (16B-aligned plane stride for ldmatrix)
#define XHL  (16 * YPL)             // 24832
#define XSM_BYTES (2 * XHL)         // 49664
#define SMEM_BYTES (WSM_BYTES + XSM_BYTES)   // 215552

__global__ __launch_bounds__(THREADS, 1)
void gbl_kernel(const float* __restrict__ x, const float* __restrict__ ref,
                const float* __restrict__ wg1, const float* __restrict__ wg2,
                const float* __restrict__ wj1, const float* __restrict__ wj2,
                float* __restrict__ out, int nPos)
{
    extern __shared__ char sm[];
    char* wsm = sm;              // [(ws*9+b)*2+hl][j 32][i 64] bf16, row 144B
    char* xsm = sm + WSM_BYTES;  // [hl][y 16][p 32][i 16] bf16, row 48B

    const int tid  = threadIdx.x;
    const int wid  = tid >> 5;
    const int lane = tid & 31;
    const int pt = wid >> 2;     // position tile (16)
    const int jt = wid & 3;      // channel tile (8)
    const int r  = lane >> 2;
    const int q  = lane & 3;

    const int group  = blockIdx.y;
    const int branch = group >> 1;
    const int chalf  = group & 1;
    const float* wA = branch ? wj1 : wg1;
    const float* wB = branch ? wj2 : wg2;

    // ---- stage weights (fp32 -> bf16 hi/lo) ----
    for (int e = tid; e < 36864; e += THREADS) {
        int ws = e / 18432;
        int rem = e - ws * 18432;
        int j = rem / 576;
        int rem2 = rem - j * 576;
        int i = rem2 / 9;
        int b = rem2 - i * 9;
        const float* src = ws ? wB : wA;
        float v = src[(chalf * 32 + j) * 576 + i * 9 + b];
        __nv_bfloat16 h = __float2bfloat16(v);
        __nv_bfloat16 l = __float2bfloat16(v - __bfloat162float(h));
        char* rp = wsm + ((ws * 9 + b) * 2) * WPL + j * JSTR + i * 2;
        *(__nv_bfloat16*)rp = h;
        *(__nv_bfloat16*)(rp + WPL) = l;
    }
    __syncthreads();

    const int cout = branch * 64 + chalf * 32 + jt * 8 + 2 * q;
    const int nChunk = nPos >> 5;
    const float4* xg4 = (const float4*)x;

    // ldmatrix per-lane base addresses
    const uint32_t wlm = smem_u32(wsm) + (jt * 8 + (lane & 7)) * JSTR
                         + ((lane >> 3) & 1) * 16;                       // + plane*WPL + ib*32
    const uint32_t xlm = smem_u32(xsm)
                         + (pt * 16 + ((lane >> 3) & 1) * 8 + (lane & 7)) * PSTR
                         + (lane >> 4) * 16;                             // + hl*XHL + y*YPL

    for (int chunk = blockIdx.x; chunk < nChunk; chunk += gridDim.x) {
        const int p0 = chunk << 5;

        float D[2][16][4];
        #pragma unroll
        for (int ws = 0; ws < 2; ws++)
            #pragma unroll
            for (int y = 0; y < 16; y++)
                #pragma unroll
                for (int k = 0; k < 4; k++) D[ws][y][k] = 0.0f;

        for (int ib = 0; ib < 4; ib++) {
            __syncthreads();
            // ---- stage x k-block: fp32 -> [hl][y][p][i] bf16 ----
            #pragma unroll
            for (int k = 0; k < 4; k++) {
                int f = tid + k * THREADS;
                int q4 = f & 3, ip = (f >> 2) & 7, p = f >> 5;
                const float4* g = xg4 + ((size_t)(p0 + p) * 64 + ib * 16 + 2 * ip) * 4 + q4;
                float4 v0 = g[0];
                float4 v1 = g[4];
                float e0[4] = {v0.x, v0.y, v0.z, v0.w};
                float e1[4] = {v1.x, v1.y, v1.z, v1.w};
                #pragma unroll
                for (int c = 0; c < 4; c++) {
                    int y = q4 * 4 + c;
                    __nv_bfloat16 h0 = __float2bfloat16(e0[c]);
                    __nv_bfloat16 h1 = __float2bfloat16(e1[c]);
                    __nv_bfloat16 l0 = __float2bfloat16(e0[c] - __bfloat162float(h0));
                    __nv_bfloat16 l1 = __float2bfloat16(e1[c] - __bfloat162float(h1));
                    uint32_t hw = (uint32_t)__bfloat16_as_ushort(h0) |
                                  ((uint32_t)__bfloat16_as_ushort(h1) << 16);
                    uint32_t lw = (uint32_t)__bfloat16_as_ushort(l0) |
                                  ((uint32_t)__bfloat16_as_ushort(l1) << 16);
                    char* d0 = xsm + y * YPL + p * PSTR + ip * 4;
                    *(uint32_t*)d0 = hw;
                    *(uint32_t*)(d0 + XHL) = lw;
                }
            }
            __syncthreads();

            // ---- resident w fragments (both wsets, hi+lo) via ldmatrix.x2 ----
            uint32_t Bw[2][9][2][2];
            const uint32_t wk = wlm + ib * 32;
            #pragma unroll
            for (int ws = 0; ws < 2; ws++)
                #pragma unroll
                for (int b = 0; b < 9; b++)
                    #pragma unroll
                    for (int hl = 0; hl < 2; hl++)
                        ldmx2(Bw[ws][b][hl], wk + ((ws * 9 + b) * 2 + hl) * WPL);

            #pragma unroll
            for (int t = 0; t < 8; t++) {
                const int ye = 2 * t, yo = 2 * t + 1;
                const int pe = PCY[ye], po = PCY[yo], bs = 4 + po;
                uint32_t Ax[2][2][4];   // [even/odd y][hi/lo]
                #pragma unroll
                for (int yy = 0; yy < 2; yy++)
                    #pragma unroll
                    for (int hl = 0; hl < 2; hl++)
                        ldmx4(Ax[yy][hl], xlm + hl * XHL + (ye + yy) * YPL);
                #pragma unroll
                for (int ws = 0; ws < 2; ws++) {
                    float* De = D[ws][ye];
                    float* Do = D[ws][yo];
                    MMA(De, Ax[0][0], Bw[ws][pe][0]);   // wh*xh
                    MMA(De, Ax[0][1], Bw[ws][pe][0]);   // wh*xl
                    MMA(De, Ax[0][0], Bw[ws][pe][1]);   // wl*xh
                    MMA(Do, Ax[1][0], Bw[ws][po][0]);
                    MMA(Do, Ax[1][1], Bw[ws][po][0]);
                    MMA(Do, Ax[1][0], Bw[ws][po][1]);
                    MMA(Do, Ax[0][0], Bw[ws][bs][0]);   // e0-shift: x[ye] -> E[yo]
                    MMA(Do, Ax[0][1], Bw[ws][bs][0]);
                    MMA(Do, Ax[0][0], Bw[ws][bs][1]);
                }
            }
        }

        // ---- bilinear epilogue + store (exact fp32) ----
        #pragma unroll
        for (int e = 0; e < 4; e++) {
            const int p = p0 + pt * 16 + r + ((e >> 1) * 8);
            const int co = cout + (e & 1);
            float o[16];
            #pragma unroll
            for (int y = 0; y < 16; y++) o[y] = 0.0f;

            if (branch == 0) {
                #pragma unroll
                for (int n = 0; n < 192; n++)
                    o[GPT.k[n]] += GPT.s[n] * D[0][GPT.a[n]][e] * D[1][GPT.b[n]][e];
                #pragma unroll
                for (int y = 0; y < 16; y++) o[y] *= 1e-5f;
            } else {
                #pragma unroll
                for (int n = 0; n < 81; n++)
                    o[JT.k[n]] += JT.s[n] * D[0][JT.a[n]][e] * D[1][JT.b[n]][e];
                const float rr = __ldg(ref + (size_t)p * 16 + 15);
                #pragma unroll
                for (int y = 0; y < 16; y++) o[y] *= rr;
            }

            float4* op = (float4*)(out + ((size_t)p * 128 + co) * 16);
            op[0] = make_float4(o[0],  o[1],  o[2],  o[3]);
            op[1] = make_float4(o[4],  o[5],  o[6],  o[7]);
            op[2] = make_float4(o[8],  o[9],  o[10], o[11]);
            op[3] = make_float4(o[12], o[13], o[14], o[15]);
        }
    }
}

extern "C" void kernel_launch(void* const* d_in, const int* in_sizes, int n_in,
                              void* d_out, int out_size) {
    const float* x   = (const float*)d_in[0];
    const float* ref = (const float*)d_in[1];
    const float* wg1 = (const float*)d_in[2];
    const float* wg2 = (const float*)d_in[3];
    const float* wj1 = (const float*)d_in[4];
    const float* wj2 = (const float*)d_in[5];
    float* out = (float*)d_out;

    const int nPos = in_sizes[0] / (64 * 16);   // 16384

    cudaFuncSetAttribute(gbl_kernel, cudaFuncAttributeMaxDynamicSharedMemorySize, SMEM_BYTES);
    dim3 grid(37, 4);
    gbl_kernel<<<grid, THREADS, SMEM_BYTES>>>(x, ref, wg1, wg2, wj1, wj2, out, nPos);
}

// round 12
// speedup vs baseline: 1.0890x; 1.0277x over previous
#include <cuda_runtime.h>
#include <cuda_bf16.h>
#include <cstdint>

__host__ __device__ constexpr int PC4(int x) {
    return ((x >> 0) & 1) + ((x >> 1) & 1) + ((x >> 2) & 1) + ((x >> 3) & 1);
}
__host__ __device__ constexpr float SGN(int a, int b) {
    int s = 0; int aa = a >> 1;
    while (aa) { s += PC4(aa & b); aa >>= 1; }
    return (s & 1) ? -1.0f : 1.0f;
}
struct GPTab { int a[192]; int b[192]; int k[192]; float s[192]; };
__host__ __device__ constexpr GPTab make_gp() {
    GPTab t{}; int n = 0;
    for (int a = 0; a < 16; a++)
        for (int b = 0; b < 16; b++)
            if (!(a & b & 1)) { t.a[n]=a; t.b[n]=b; t.k[n]=a^b; t.s[n]=SGN(a,b); n++; }
    return t;
}
struct JTab { int a[81]; int b[81]; int k[81]; float s[81]; };
__host__ __device__ constexpr JTab make_j() {
    JTab t{}; int n = 0;
    for (int i = 0; i < 16; i++)
        for (int j = 0; j < 16; j++)
            if ((i | j) == 15) {
                int p = i^15, q = j^15, k = i&j, r = k^15;
                t.a[n]=i; t.b[n]=j; t.k[n]=k;
                t.s[n]=SGN(i,p)*SGN(j,q)*SGN(p,q)*SGN(k,r); n++;
            }
    return t;
}
__device__ constexpr GPTab GPT = make_gp();
__device__ constexpr JTab  JT  = make_j();
__device__ constexpr int PCY[16] = {0,1,1,2,1,2,2,3,1,2,2,3,2,3,3,4};

#define MMA(d, a, b) \
    asm("mma.sync.aligned.m16n8k16.row.col.f32.bf16.bf16.f32 " \
        "{%0,%1,%2,%3}, {%4,%5,%6,%7}, {%8,%9}, {%0,%1,%2,%3};" \
        : "+f"(d[0]), "+f"(d[1]), "+f"(d[2]), "+f"(d[3]) \
        : "r"(a[0]), "r"(a[1]), "r"(a[2]), "r"(a[3]), "r"(b[0]), "r"(b[1]))

__device__ __forceinline__ void ldmx4(uint32_t* r, uint32_t a) {
    asm volatile("ldmatrix.sync.aligned.m8n8.x4.shared.b16 {%0,%1,%2,%3}, [%4];"
        : "=r"(r[0]), "=r"(r[1]), "=r"(r[2]), "=r"(r[3]) : "r"(a));
}
__device__ __forceinline__ void ldmx2(uint32_t* r, uint32_t a) {
    asm volatile("ldmatrix.sync.aligned.m8n8.x2.shared.b16 {%0,%1}, [%2];"
        : "=r"(r[0]), "=r"(r[1]) : "r"(a));
}
__device__ __forceinline__ uint32_t smem_u32(const void* p) {
    uint32_t a;
    asm("{ .reg .u64 t; cvta.to.shared.u64 t, %1; cvt.u32.u64 %0, t; }" : "=r"(a) : "l"(p));
    return a;
}

#define THREADS 256
#define JSTR 144
#define WPL  (32 * JSTR)            // 4608 per (ws,b,hl) plane
#define WSM_BYTES (36 * WPL)        // 165888
#define PSTR 48
#define YPL  (32 * PSTR + 16)       // 1552 (16B-aligned plane stride)
#define XHL  (16 * YPL)             // 24832
#define XSM_BYTES (2 * XHL)
#define SMEM_BYTES (WSM_BYTES + XSM_BYTES)

__global__ __launch_bounds__(THREADS, 1)
void gbl_kernel(const float* __restrict__ x, const float* __restrict__ ref,
                const float* __restrict__ wg1, const float* __restrict__ wg2,
                const float* __restrict__ wj1, const float* __restrict__ wj2,
                float* __restrict__ out, int nPos)
{
    extern __shared__ char sm[];
    char* wsm = sm;
    char* xsm = sm + WSM_BYTES;

    const int tid  = threadIdx.x;
    const int wid  = tid >> 5;
    const int lane = tid & 31;
    const int pt = wid >> 2;
    const int jt = wid & 3;
    const int r  = lane >> 2;
    const int q  = lane & 3;

    const int group  = blockIdx.y;
    const int branch = group >> 1;
    const int chalf  = group & 1;
    const float* wA = branch ? wj1 : wg1;
    const float* wB = branch ? wj2 : wg2;

    for (int e = tid; e < 36864; e += THREADS) {
        int ws = e / 18432;
        int rem = e - ws * 18432;
        int j = rem / 576;
        int rem2 = rem - j * 576;
        int i = rem2 / 9;
        int b = rem2 - i * 9;
        const float* src = ws ? wB : wA;
        float v = src[(chalf * 32 + j) * 576 + i * 9 + b];
        __nv_bfloat16 h = __float2bfloat16(v);
        __nv_bfloat16 l = __float2bfloat16(v - __bfloat162float(h));
        char* rp = wsm + ((ws * 9 + b) * 2) * WPL + j * JSTR + i * 2;
        *(__nv_bfloat16*)rp = h;
        *(__nv_bfloat16*)(rp + WPL) = l;
    }
    __syncthreads();

    const int cout = branch * 64 + chalf * 32 + jt * 8 + 2 * q;
    const int nChunk = nPos >> 5;
    const float4* xg4 = (const float4*)x;

    const uint32_t wlm = smem_u32(wsm) + (jt * 8 + (lane & 7)) * JSTR
                         + ((lane >> 3) & 1) * 16;
    const uint32_t xlm = smem_u32(xsm)
                         + (pt * 16 + ((lane >> 3) & 1) * 8 + (lane & 7)) * PSTR
                         + (lane >> 4) * 16;

    // staging thread mapping (constant per thread)
    const int sq4 = tid & 3, sip = (tid >> 2) & 7;
    const int sp0 = tid >> 5, sp1 = (tid + THREADS) >> 5,
              sp2 = (tid + 2 * THREADS) >> 5, sp3 = (tid + 3 * THREADS) >> 5;
    const int spp[4] = {sp0, sp1, sp2, sp3};

    // ---- prefetch first k-block of first chunk ----
    float4 pf[8];
    #pragma unroll
    for (int k = 0; k < 4; k++) {
        const float4* g = xg4 + ((size_t)((blockIdx.x << 5) + spp[k]) * 64 + 2 * sip) * 4 + sq4;
        pf[2 * k]     = g[0];
        pf[2 * k + 1] = g[4];
    }

    for (int chunk = blockIdx.x; chunk < nChunk; chunk += gridDim.x) {
        const int p0 = chunk << 5;

        float D[2][16][4];
        #pragma unroll
        for (int ws = 0; ws < 2; ws++)
            #pragma unroll
            for (int y = 0; y < 16; y++)
                #pragma unroll
                for (int k = 0; k < 4; k++) D[ws][y][k] = 0.0f;

        for (int ib = 0; ib < 4; ib++) {
            __syncthreads();
            // ---- convert + store prefetched k-block ----
            #pragma unroll
            for (int k = 0; k < 4; k++) {
                float e0[4] = {pf[2*k].x, pf[2*k].y, pf[2*k].z, pf[2*k].w};
                float e1[4] = {pf[2*k+1].x, pf[2*k+1].y, pf[2*k+1].z, pf[2*k+1].w};
                #pragma unroll
                for (int c = 0; c < 4; c++) {
                    int y = sq4 * 4 + c;
                    __nv_bfloat16 h0 = __float2bfloat16(e0[c]);
                    __nv_bfloat16 h1 = __float2bfloat16(e1[c]);
                    __nv_bfloat16 l0 = __float2bfloat16(e0[c] - __bfloat162float(h0));
                    __nv_bfloat16 l1 = __float2bfloat16(e1[c] - __bfloat162float(h1));
                    uint32_t hw = (uint32_t)__bfloat16_as_ushort(h0) |
                                  ((uint32_t)__bfloat16_as_ushort(h1) << 16);
                    uint32_t lw = (uint32_t)__bfloat16_as_ushort(l0) |
                                  ((uint32_t)__bfloat16_as_ushort(l1) << 16);
                    char* d0 = xsm + y * YPL + spp[k] * PSTR + sip * 4;
                    *(uint32_t*)d0 = hw;
                    *(uint32_t*)(d0 + XHL) = lw;
                }
            }
            __syncthreads();

            // ---- prefetch next k-block (or next chunk's first) ----
            {
                int nib = ib + 1;
                int nch = chunk;
                if (nib == 4) { nib = 0; nch = chunk + gridDim.x; }
                if (nch < nChunk) {
                    const int np0 = nch << 5;
                    #pragma unroll
                    for (int k = 0; k < 4; k++) {
                        const float4* g = xg4 + ((size_t)(np0 + spp[k]) * 64 + nib * 16 + 2 * sip) * 4 + sq4;
                        pf[2 * k]     = g[0];
                        pf[2 * k + 1] = g[4];
                    }
                }
            }

            // ---- hi w fragments cached (both wsets) ----
            uint32_t Bh[2][9][2];
            const uint32_t wk = wlm + ib * 32;
            #pragma unroll
            for (int ws = 0; ws < 2; ws++)
                #pragma unroll
                for (int b = 0; b < 9; b++)
                    ldmx2(Bh[ws][b], wk + ((ws * 9 + b) * 2) * WPL);

            #pragma unroll
            for (int t = 0; t < 8; t++) {
                const int ye = 2 * t, yo = 2 * t + 1;
                const int pe = PCY[ye], po = PCY[yo], bs = 4 + po;
                uint32_t Ax[2][2][4];
                #pragma unroll
                for (int yy = 0; yy < 2; yy++)
                    #pragma unroll
                    for (int hl = 0; hl < 2; hl++)
                        ldmx4(Ax[yy][hl], xlm + hl * XHL + (ye + yy) * YPL);
                uint32_t Blp[2][2], Blo[2][2], Blb[2][2];
                #pragma unroll
                for (int ws = 0; ws < 2; ws++) {
                    ldmx2(Blp[ws], wk + ((ws * 9 + pe) * 2 + 1) * WPL);
                    ldmx2(Blo[ws], wk + ((ws * 9 + po) * 2 + 1) * WPL);
                    ldmx2(Blb[ws], wk + ((ws * 9 + bs) * 2 + 1) * WPL);
                }
                // interleaved issue: consecutive MMAs never share an accumulator
                #pragma unroll
                for (int ws = 0; ws < 2; ws++) MMA(D[ws][ye], Ax[0][0], Bh[ws][pe]);
                #pragma unroll
                for (int ws = 0; ws < 2; ws++) MMA(D[ws][yo], Ax[1][0], Bh[ws][po]);
                #pragma unroll
                for (int ws = 0; ws < 2; ws++) MMA(D[ws][ye], Ax[0][1], Bh[ws][pe]);
                #pragma unroll
                for (int ws = 0; ws < 2; ws++) MMA(D[ws][yo], Ax[1][1], Bh[ws][po]);
                #pragma unroll
                for (int ws = 0; ws < 2; ws++) MMA(D[ws][ye], Ax[0][0], Blp[ws]);
                #pragma unroll
                for (int ws = 0; ws < 2; ws++) MMA(D[ws][yo], Ax[1][0], Blo[ws]);
                #pragma unroll
                for (int ws = 0; ws < 2; ws++) MMA(D[ws][yo], Ax[0][0], Bh[ws][bs]);
                #pragma unroll
                for (int ws = 0; ws < 2; ws++) MMA(D[ws][yo], Ax[0][1], Bh[ws][bs]);
                #pragma unroll
                for (int ws = 0; ws < 2; ws++) MMA(D[ws][yo], Ax[0][0], Blb[ws]);
            }
        }

        // ---- bilinear epilogue + store (exact fp32) ----
        #pragma unroll
        for (int e = 0; e < 4; e++) {
            const int p = p0 + pt * 16 + r + ((e >> 1) * 8);
            const int co = cout + (e & 1);
            float o[16];
            #pragma unroll
            for (int y = 0; y < 16; y++) o[y] = 0.0f;

            if (branch == 0) {
                #pragma unroll
                for (int n = 0; n < 192; n++)
                    o[GPT.k[n]] += GPT.s[n] * D[0][GPT.a[n]][e] * D[1][GPT.b[n]][e];
                #pragma unroll
                for (int y = 0; y < 16; y++) o[y] *= 1e-5f;
            } else {
                #pragma unroll
                for (int n = 0; n < 81; n++)
                    o[JT.k[n]] += JT.s[n] * D[0][JT.a[n]][e] * D[1][JT.b[n]][e];
                const float rr = __ldg(ref + (size_t)p * 16 + 15);
                #pragma unroll
                for (int y = 0; y < 16; y++) o[y] *= rr;
            }

            float4* op = (float4*)(out + ((size_t)p * 128 + co) * 16);
            op[0] = make_float4(o[0],  o[1],  o[2],  o[3]);
            op[1] = make_float4(o[4],  o[5],  o[6],  o[7]);
            op[2] = make_float4(o[8],  o[9],  o[10], o[11]);
            op[3] = make_float4(o[12], o[13], o[14], o[15]);
        }
    }
}

extern "C" void kernel_launch(void* const* d_in, const int* in_sizes, int n_in,
                              void* d_out, int out_size) {
    const float* x   = (const float*)d_in[0];
    const float* ref = (const float*)d_in[1];
    const float* wg1 = (const float*)d_in[2];
    const float* wg2 = (const float*)d_in[3];
    const float* wj1 = (const float*)d_in[4];
    const float* wj2 = (const float*)d_in[5];
    float* out = (float*)d_out;

    const int nPos = in_sizes[0] / (64 * 16);   // 16384

    cudaFuncSetAttribute(gbl_kernel, cudaFuncAttributeMaxDynamicSharedMemorySize, SMEM_BYTES);
    dim3 grid(37, 4);
    gbl_kernel<<<grid, THREADS, SMEM_BYTES>>>(x, ref, wg1, wg2, wj1, wj2, out, nPos);
}